// round 11
// baseline (speedup 1.0000x reference)
#include <cuda_runtime.h>
#include <cuda_bf16.h>
#include <cstdint>

constexpr int TOKENS = 8192;
constexpr int INF    = 4096;
constexpr int RANK   = 1024;
constexpr int OUTF   = 4096;

// ---------------- static device scratch (no allocs allowed) ----------------
__device__ __nv_bfloat16 g_x1[(size_t)TOKENS * INF];
__device__ __nv_bfloat16 g_x2[(size_t)TOKENS * INF];
__device__ __nv_bfloat16 g_x3[(size_t)TOKENS * INF];
__device__ __nv_bfloat16 g_w1[(size_t)RANK * INF];
__device__ __nv_bfloat16 g_w2[(size_t)RANK * INF];
__device__ __nv_bfloat16 g_w3[(size_t)RANK * INF];
__device__ int8_t        g_ia1[(size_t)OUTF * RANK];
__device__ int8_t        g_ia2[(size_t)OUTF * RANK];
__device__ float         g_s1[OUTF];
__device__ float         g_s2[OUTF];
__device__ int8_t        g_qi[(size_t)TOKENS * RANK];
__device__ float         g_y [(size_t)TOKENS * RANK];
__device__ int           g_amax_bits;

// ---------------- low-level helpers (baseline PTX, sm_80+) ----------------
__device__ __forceinline__ uint32_t smem_u32(const void* p) {
    uint32_t a;
    asm("{ .reg .u64 t; cvta.to.shared.u64 t, %1; cvt.u32.u64 %0, t; }" : "=r"(a) : "l"(p));
    return a;
}
__device__ __forceinline__ void cpa16(uint32_t s, const void* g) {
    asm volatile("cp.async.cg.shared.global [%0], [%1], 16;" :: "r"(s), "l"(g));
}
__device__ __forceinline__ void cpa_commit() { asm volatile("cp.async.commit_group;" ::: "memory"); }
__device__ __forceinline__ void cpa_wait1()  { asm volatile("cp.async.wait_group 1;" ::: "memory"); }

__device__ __forceinline__ void ldsm4(uint32_t* r, uint32_t a) {
    asm volatile("ldmatrix.sync.aligned.m8n8.x4.shared.b16 {%0,%1,%2,%3}, [%4];"
                 : "=r"(r[0]), "=r"(r[1]), "=r"(r[2]), "=r"(r[3]) : "r"(a));
}
__device__ __forceinline__ void mma_bf16(float* d, const uint32_t* a, const uint32_t* b) {
    asm volatile(
        "mma.sync.aligned.m16n8k16.row.col.f32.bf16.bf16.f32 "
        "{%0,%1,%2,%3}, {%4,%5,%6,%7}, {%8,%9}, {%0,%1,%2,%3};"
        : "+f"(d[0]), "+f"(d[1]), "+f"(d[2]), "+f"(d[3])
        : "r"(a[0]), "r"(a[1]), "r"(a[2]), "r"(a[3]), "r"(b[0]), "r"(b[1]));
}
__device__ __forceinline__ void mma_s8(int* d, const uint32_t* a, const uint32_t* b) {
    asm volatile(
        "mma.sync.aligned.m16n8k32.row.col.s32.s8.s8.s32 "
        "{%0,%1,%2,%3}, {%4,%5,%6,%7}, {%8,%9}, {%0,%1,%2,%3};"
        : "+r"(d[0]), "+r"(d[1]), "+r"(d[2]), "+r"(d[3])
        : "r"(a[0]), "r"(a[1]), "r"(a[2]), "r"(a[3]), "r"(b[0]), "r"(b[1]));
}
// 128B rows of 8 x 16B chunks; xor-swizzle -> conflict-free ldmatrix & stores
__device__ __forceinline__ uint32_t sw(uint32_t row, uint32_t ch) {
    return row * 128u + ((ch ^ (row & 7u)) * 16u);
}
// WELL-DEFINED float -> int8 (round half-to-even). Plain (char) is UNSIGNED on
// aarch64 and float->u8 saturates negatives to 0 -- the R10 bug.
__device__ __forceinline__ signed char f2i8(float f) {
    return (signed char)__float2int_rn(f);
}

// ---------------- prep kernels ----------------
__global__ void k_reset() { g_amax_bits = 0; }

__global__ void k_split3(const float* __restrict__ s, __nv_bfloat16* __restrict__ d1,
                         __nv_bfloat16* __restrict__ d2, __nv_bfloat16* __restrict__ d3, int n2) {
    int i = blockIdx.x * blockDim.x + threadIdx.x;
    if (i >= n2) return;
    float2 v = reinterpret_cast<const float2*>(s)[i];
    float f[2] = {v.x, v.y};
    __nv_bfloat16 h1[2], h2[2], h3[2];
#pragma unroll
    for (int j = 0; j < 2; j++) {
        h1[j] = __float2bfloat16_rn(f[j]);
        float r  = __fsub_rn(f[j], __bfloat162float(h1[j]));   // exact
        h2[j] = __float2bfloat16_rn(r);
        float r2 = __fsub_rn(r, __bfloat162float(h2[j]));      // exact
        h3[j] = __float2bfloat16_rn(r2);                       // exact (27>=24 bits)
    }
    reinterpret_cast<__nv_bfloat162*>(d1)[i] = __halves2bfloat162(h1[0], h1[1]);
    reinterpret_cast<__nv_bfloat162*>(d2)[i] = __halves2bfloat162(h2[0], h2[1]);
    reinterpret_cast<__nv_bfloat162*>(d3)[i] = __halves2bfloat162(h3[0], h3[1]);
}

// Per-row 2-limb int8 quantization of A_w: A[n,:] ~= a1*s1[n] + a2*s2[n]
__global__ __launch_bounds__(256)
void k_aq(const float* __restrict__ A, int8_t* __restrict__ a1, int8_t* __restrict__ a2,
          float* __restrict__ s1, float* __restrict__ s2) {
    const int row = blockIdx.x, t = threadIdx.x, lane = t & 31, wid = t >> 5;
    __shared__ float red[8];
    __shared__ float bcast;

    const float4 v = reinterpret_cast<const float4*>(A + (size_t)row * RANK)[t];
    float f[4] = {v.x, v.y, v.z, v.w};

    // reduce amax(|A|) over the row
    float am = fmaxf(fmaxf(fabsf(f[0]), fabsf(f[1])), fmaxf(fabsf(f[2]), fabsf(f[3])));
#pragma unroll
    for (int o = 16; o > 0; o >>= 1) am = fmaxf(am, __shfl_xor_sync(0xffffffffu, am, o));
    if (lane == 0) red[wid] = am;
    __syncthreads();
    if (t == 0) {
        float m = red[0];
#pragma unroll
        for (int w = 1; w < 8; w++) m = fmaxf(m, red[w]);
        bcast = __fdiv_rn(fmaxf(m, 1e-30f), 127.0f);
    }
    __syncthreads();
    const float s1v = bcast;

    float q1[4], r[4];
#pragma unroll
    for (int j = 0; j < 4; j++) {
        q1[j] = rintf(__fdiv_rn(f[j], s1v));
        r[j]  = __fsub_rn(f[j], __fmul_rn(q1[j], s1v));
    }
    // reduce amax(|residual|)
    float am2 = fmaxf(fmaxf(fabsf(r[0]), fabsf(r[1])), fmaxf(fabsf(r[2]), fabsf(r[3])));
#pragma unroll
    for (int o = 16; o > 0; o >>= 1) am2 = fmaxf(am2, __shfl_xor_sync(0xffffffffu, am2, o));
    __syncthreads();
    if (lane == 0) red[wid] = am2;
    __syncthreads();
    if (t == 0) {
        float m = red[0];
#pragma unroll
        for (int w = 1; w < 8; w++) m = fmaxf(m, red[w]);
        bcast = __fdiv_rn(fmaxf(m, 1e-30f), 127.0f);
    }
    __syncthreads();
    const float s2v = bcast;

    char4 c1, c2;
    c1.x = f2i8(q1[0]); c1.y = f2i8(q1[1]); c1.z = f2i8(q1[2]); c1.w = f2i8(q1[3]);
    c2.x = f2i8(__fdiv_rn(r[0], s2v));
    c2.y = f2i8(__fdiv_rn(r[1], s2v));
    c2.z = f2i8(__fdiv_rn(r[2], s2v));
    c2.w = f2i8(__fdiv_rn(r[3], s2v));
    reinterpret_cast<char4*>(a1 + (size_t)row * RANK)[t] = c1;
    reinterpret_cast<char4*>(a2 + (size_t)row * RANK)[t] = c2;
    if (t == 0) { s1[row] = s1v; s2[row] = s2v; }
}

// q = clip(round(y/scale), -4, 3), exact int8
__global__ void k_quant(const float* __restrict__ y, int8_t* __restrict__ q, int n4) {
    const float amax  = __int_as_float(g_amax_bits);
    const float scale = __fdiv_rn(fmaxf(amax, 1e-8f), 3.0f);
    int i = blockIdx.x * blockDim.x + threadIdx.x;
    if (i >= n4) return;
    float4 v = reinterpret_cast<const float4*>(y)[i];
    char4 c;
    c.x = f2i8(fminf(fmaxf(rintf(__fdiv_rn(v.x, scale)), -4.f), 3.f));
    c.y = f2i8(fminf(fmaxf(rintf(__fdiv_rn(v.y, scale)), -4.f), 3.f));
    c.z = f2i8(fminf(fmaxf(rintf(__fdiv_rn(v.z, scale)), -4.f), 3.f));
    c.w = f2i8(fminf(fmaxf(rintf(__fdiv_rn(v.w, scale)), -4.f), 3.f));
    reinterpret_cast<char4*>(q)[i] = c;
}

// ---------------------------------------------------------------------------
// GEMM1: y = x @ B_w^T via 6 limb products on mma.sync bf16 (unchanged from R9).
// Block 128x64, BK=64, 256 threads = 8 warps (4m x 2n), warp tile 32x32.
// ---------------------------------------------------------------------------
constexpr int G1_STAGE = 3 * 16384 + 3 * 8192;
constexpr int G1_SMEM  = 3 * G1_STAGE;           // 216 KB

__global__ __launch_bounds__(256, 1)
void gemm1_mma(const __nv_bfloat16* __restrict__ X1, const __nv_bfloat16* __restrict__ X2,
               const __nv_bfloat16* __restrict__ X3, const __nv_bfloat16* __restrict__ W1,
               const __nv_bfloat16* __restrict__ W2, const __nv_bfloat16* __restrict__ W3,
               float* __restrict__ Y)
{
    extern __shared__ char smem_raw[];
    const uint32_t sbu = smem_u32(smem_raw);
    const int tid = threadIdx.x, lane = tid & 31, wid = tid >> 5;
    const int wm = wid & 3, wn = wid >> 2;
    const int m0 = blockIdx.y * 128, n0 = blockIdx.x * 64;

    const __nv_bfloat16* AP[3] = {X1, X2, X3};
    const __nv_bfloat16* BP[3] = {W1, W2, W3};

    float acc[32], cmp[32];
#pragma unroll
    for (int c = 0; c < 32; c++) { acc[c] = 0.f; cmp[c] = 0.f; }

    auto load_stage = [&](int kt, int buf) {
        const uint32_t sb = sbu + buf * G1_STAGE;
        const int k0 = kt * 64;
#pragma unroll
        for (int l = 0; l < 3; l++) {
#pragma unroll
            for (int it = 0; it < 4; it++) {
                int i = tid + it * 256;
                int row = i >> 3, ch = i & 7;
                cpa16(sb + l * 16384 + sw(row, ch),
                      AP[l] + (size_t)(m0 + row) * INF + k0 + ch * 8);
            }
#pragma unroll
            for (int it = 0; it < 2; it++) {
                int i = tid + it * 256;
                int row = i >> 3, ch = i & 7;
                cpa16(sb + 49152 + l * 8192 + sw(row, ch),
                      BP[l] + (size_t)(n0 + row) * INF + k0 + ch * 8);
            }
        }
    };

    load_stage(0, 0); cpa_commit();
    load_stage(1, 1); cpa_commit();

    const int tA = lane >> 3, rA = lane & 7;
    const uint32_t arow  = wm * 32 + (tA & 1) * 8 + rA;
    const uint32_t brow0 = wn * 32 +      ((lane >> 4) & 1) * 8 + (lane & 7);
    const uint32_t brow1 = wn * 32 + 16 + ((lane >> 4) & 1) * 8 + (lane & 7);
    const uint32_t bch   = (lane >> 3) & 1;

    for (int kt = 0; kt < 64; kt++) {
        cpa_wait1();
        __syncthreads();

        const uint32_t sb = sbu + (kt % 3) * G1_STAGE;
        float chunk[32];
#pragma unroll
        for (int c = 0; c < 32; c++) chunk[c] = 0.f;

#pragma unroll
        for (int al = 2; al >= 0; al--) {
            uint32_t aF[2][4][4];
            const uint32_t ta = sb + al * 16384;
#pragma unroll
            for (int mi = 0; mi < 2; mi++)
#pragma unroll
                for (int ks = 0; ks < 4; ks++)
                    ldsm4(aF[mi][ks], ta + sw(arow + mi * 16, ks * 2 + (tA >> 1)));
            const int nb = (al == 0) ? 3 : (al == 1 ? 2 : 1);
#pragma unroll
            for (int bl = 2; bl >= 0; bl--) {
                if (bl >= nb) continue;
                const uint32_t tb = sb + 49152 + bl * 8192;
#pragma unroll
                for (int ks = 0; ks < 4; ks++) {
                    uint32_t bF[4], bG[4];
                    ldsm4(bF, tb + sw(brow0, ks * 2 + bch));
                    ldsm4(bG, tb + sw(brow1, ks * 2 + bch));
                    mma_bf16(&chunk[0],  aF[0][ks], bF + 0);
                    mma_bf16(&chunk[16], aF[1][ks], bF + 0);
                    mma_bf16(&chunk[4],  aF[0][ks], bF + 2);
                    mma_bf16(&chunk[20], aF[1][ks], bF + 2);
                    mma_bf16(&chunk[8],  aF[0][ks], bG + 0);
                    mma_bf16(&chunk[24], aF[1][ks], bG + 0);
                    mma_bf16(&chunk[12], aF[0][ks], bG + 2);
                    mma_bf16(&chunk[28], aF[1][ks], bG + 2);
                }
            }
        }

#pragma unroll
        for (int c = 0; c < 32; c++) {
            float yk = __fsub_rn(chunk[c], cmp[c]);
            float t  = __fadd_rn(acc[c], yk);
            cmp[c]   = __fsub_rn(__fsub_rn(t, acc[c]), yk);
            acc[c]   = t;
        }

        if (kt + 2 < 64) load_stage(kt + 2, (kt + 2) % 3);
        cpa_commit();
    }

    float v[32];
    float lmax = 0.f;
#pragma unroll
    for (int c = 0; c < 32; c++) {
        v[c] = __fsub_rn(acc[c], cmp[c]);
        lmax = fmaxf(lmax, fabsf(v[c]));
    }
#pragma unroll
    for (int o = 16; o > 0; o >>= 1)
        lmax = fmaxf(lmax, __shfl_xor_sync(0xffffffffu, lmax, o));
    if (lane == 0) atomicMax(&g_amax_bits, __float_as_int(lmax));

    const int rbase = m0 + wm * 32 + (lane >> 2);
    const int cbase = n0 + wn * 32 + (lane & 3) * 2;
#pragma unroll
    for (int mi = 0; mi < 2; mi++)
#pragma unroll
        for (int ni = 0; ni < 4; ni++) {
            const float* f = &v[mi * 16 + ni * 4];
            float* p0 = Y + (size_t)(rbase + mi * 16)     * RANK + cbase + ni * 8;
            float* p1 = Y + (size_t)(rbase + mi * 16 + 8) * RANK + cbase + ni * 8;
            *reinterpret_cast<float2*>(p0) = make_float2(f[0], f[1]);
            *reinterpret_cast<float2*>(p1) = make_float2(f[2], f[3]);
        }
}

// ---------------------------------------------------------------------------
// GEMM2 (int8 IMMA): out = (q @ (a1*s1[n] + a2*s2[n])^T) * scale + bias.
// Exact integer accumulation. Block 128x64, BK=128 int8 (8 kt iters),
// 256 threads = 8 warps (4m x 2n), warp tile 32x32, 3-stage pipeline.
// ---------------------------------------------------------------------------
constexpr int G2_STAGE = 16384 + 2 * 8192;   // q (128x128 i8) + a1,a2 (64x128 i8)
constexpr int G2_SMEM  = 3 * G2_STAGE;       // 96 KB

__global__ __launch_bounds__(256, 1)
void gemm2_imma(const int8_t* __restrict__ Q, const int8_t* __restrict__ A1,
                const int8_t* __restrict__ A2, const float* __restrict__ S1,
                const float* __restrict__ S2, const float* __restrict__ bias,
                float* __restrict__ Out)
{
    extern __shared__ char smem_raw[];
    const uint32_t sbu = smem_u32(smem_raw);
    const int tid = threadIdx.x, lane = tid & 31, wid = tid >> 5;
    const int wm = wid & 3, wn = wid >> 2;
    const int m0 = blockIdx.y * 128, n0 = blockIdx.x * 64;

    const int8_t* BP[2] = {A1, A2};

    int acc1[32], acc2[32];
#pragma unroll
    for (int c = 0; c < 32; c++) { acc1[c] = 0; acc2[c] = 0; }

    auto load_stage = [&](int kt, int buf) {
        const uint32_t sb = sbu + buf * G2_STAGE;
        const int k0 = kt * 128;
#pragma unroll
        for (int it = 0; it < 4; it++) {
            int i = tid + it * 256;
            int row = i >> 3, ch = i & 7;
            cpa16(sb + sw(row, ch), Q + (size_t)(m0 + row) * RANK + k0 + ch * 16);
        }
#pragma unroll
        for (int l = 0; l < 2; l++)
#pragma unroll
            for (int it = 0; it < 2; it++) {
                int i = tid + it * 256;
                int row = i >> 3, ch = i & 7;
                cpa16(sb + 16384 + l * 8192 + sw(row, ch),
                      BP[l] + (size_t)(n0 + row) * RANK + k0 + ch * 16);
            }
    };

    load_stage(0, 0); cpa_commit();
    load_stage(1, 1); cpa_commit();

    const int tA = lane >> 3, rA = lane & 7;
    const uint32_t arow  = wm * 32 + (tA & 1) * 8 + rA;
    const uint32_t brow0 = wn * 32 +      ((lane >> 4) & 1) * 8 + (lane & 7);
    const uint32_t brow1 = wn * 32 + 16 + ((lane >> 4) & 1) * 8 + (lane & 7);
    const uint32_t bch   = (lane >> 3) & 1;

    for (int kt = 0; kt < 8; kt++) {
        cpa_wait1();
        __syncthreads();

        const uint32_t sb = sbu + (kt % 3) * G2_STAGE;
        uint32_t aF[2][4][4];
#pragma unroll
        for (int mi = 0; mi < 2; mi++)
#pragma unroll
            for (int ks = 0; ks < 4; ks++)
                ldsm4(aF[mi][ks], sb + sw(arow + mi * 16, ks * 2 + (tA >> 1)));
#pragma unroll
        for (int bl = 1; bl >= 0; bl--) {
            const uint32_t tb = sb + 16384 + bl * 8192;
            int* acc = (bl == 0) ? acc1 : acc2;
#pragma unroll
            for (int ks = 0; ks < 4; ks++) {
                uint32_t bF[4], bG[4];
                ldsm4(bF, tb + sw(brow0, ks * 2 + bch));
                ldsm4(bG, tb + sw(brow1, ks * 2 + bch));
                mma_s8(&acc[0],  aF[0][ks], bF + 0);
                mma_s8(&acc[16], aF[1][ks], bF + 0);
                mma_s8(&acc[4],  aF[0][ks], bF + 2);
                mma_s8(&acc[20], aF[1][ks], bF + 2);
                mma_s8(&acc[8],  aF[0][ks], bG + 0);
                mma_s8(&acc[24], aF[1][ks], bG + 0);
                mma_s8(&acc[12], aF[0][ks], bG + 2);
                mma_s8(&acc[28], aF[1][ks], bG + 2);
            }
        }

        if (kt + 2 < 8) load_stage(kt + 2, (kt + 2) % 3);
        cpa_commit();
    }

    // ---- epilogue: combine limbs, scale + bias ----
    const float amax  = __int_as_float(g_amax_bits);
    const float scale = __fdiv_rn(fmaxf(amax, 1e-8f), 3.0f);
    const int rbase = m0 + wm * 32 + (lane >> 2);
    const int cbase = n0 + wn * 32 + (lane & 3) * 2;
#pragma unroll
    for (int mi = 0; mi < 2; mi++)
#pragma unroll
        for (int ni = 0; ni < 4; ni++) {
            const int c0 = mi * 16 + ni * 4;
            const int col = cbase + ni * 8;
            const float s1a = __ldg(S1 + col),     s2a = __ldg(S2 + col);
            const float s1b = __ldg(S1 + col + 1), s2b = __ldg(S2 + col + 1);
            const float b0 = __ldg(bias + col), b1 = __ldg(bias + col + 1);
            float f0 = __fadd_rn(__fmul_rn((float)acc1[c0 + 0], s1a), __fmul_rn((float)acc2[c0 + 0], s2a));
            float f1 = __fadd_rn(__fmul_rn((float)acc1[c0 + 1], s1b), __fmul_rn((float)acc2[c0 + 1], s2b));
            float f2 = __fadd_rn(__fmul_rn((float)acc1[c0 + 2], s1a), __fmul_rn((float)acc2[c0 + 2], s2a));
            float f3 = __fadd_rn(__fmul_rn((float)acc1[c0 + 3], s1b), __fmul_rn((float)acc2[c0 + 3], s2b));
            float* p0 = Out + (size_t)(rbase + mi * 16)     * OUTF + col;
            float* p1 = Out + (size_t)(rbase + mi * 16 + 8) * OUTF + col;
            *reinterpret_cast<float2*>(p0) =
                make_float2(__fadd_rn(__fmul_rn(f0, scale), b0),
                            __fadd_rn(__fmul_rn(f1, scale), b1));
            *reinterpret_cast<float2*>(p1) =
                make_float2(__fadd_rn(__fmul_rn(f2, scale), b0),
                            __fadd_rn(__fmul_rn(f3, scale), b1));
        }
}

// ---------------------------------------------------------------------------
extern "C" void kernel_launch(void* const* d_in, const int* in_sizes, int n_in,
                              void* d_out, int out_size)
{
    const float* input = (const float*)d_in[0];
    const float* B_w   = (const float*)d_in[1];
    const float* A_w   = (const float*)d_in[2];
    const float* A_b   = (const float*)d_in[3];
    float*       out   = (float*)d_out;

    __nv_bfloat16 *x1, *x2, *x3, *w1, *w2, *w3;
    int8_t *ia1, *ia2, *qi;
    float *s1, *s2, *y;
    cudaGetSymbolAddress((void**)&x1, g_x1); cudaGetSymbolAddress((void**)&x2, g_x2);
    cudaGetSymbolAddress((void**)&x3, g_x3); cudaGetSymbolAddress((void**)&w1, g_w1);
    cudaGetSymbolAddress((void**)&w2, g_w2); cudaGetSymbolAddress((void**)&w3, g_w3);
    cudaGetSymbolAddress((void**)&ia1, g_ia1); cudaGetSymbolAddress((void**)&ia2, g_ia2);
    cudaGetSymbolAddress((void**)&s1, g_s1);  cudaGetSymbolAddress((void**)&s2, g_s2);
    cudaGetSymbolAddress((void**)&qi, g_qi);  cudaGetSymbolAddress((void**)&y,  g_y);

    cudaFuncSetAttribute(gemm1_mma,  cudaFuncAttributeMaxDynamicSharedMemorySize, G1_SMEM);
    cudaFuncSetAttribute(gemm2_imma, cudaFuncAttributeMaxDynamicSharedMemorySize, G2_SMEM);

    k_reset<<<1, 1>>>();

    {   // limb splits + A_w int8 quantization
        int n2 = TOKENS * INF / 2;
        k_split3<<<(n2 + 255) / 256, 256>>>(input, x1, x2, x3, n2);
        n2 = RANK * INF / 2;
        k_split3<<<(n2 + 255) / 256, 256>>>(B_w, w1, w2, w3, n2);
        k_aq<<<OUTF, 256>>>(A_w, ia1, ia2, s1, s2);
    }

    {   // y = x @ B_w^T  (tensor cores, fused amax)
        dim3 grid(RANK / 64, TOKENS / 128);
        gemm1_mma<<<grid, 256, G1_SMEM>>>(x1, x2, x3, w1, w2, w3, y);
    }

    {   // q = clip(round(y/scale)) as int8
        const int n4 = TOKENS * RANK / 4;
        k_quant<<<(n4 + 255) / 256, 256>>>(y, qi, n4);
    }

    {   // out = q @ A^T * scale + bias  (exact int8 IMMA)
        dim3 grid(OUTF / 64, TOKENS / 128);
        gemm2_imma<<<grid, 256, G2_SMEM>>>(qi, ia1, ia2, s1, s2, A_b, out);
    }
}

// round 12
// speedup vs baseline: 1.3862x; 1.3862x over previous
#include <cuda_runtime.h>
#include <cuda_bf16.h>
#include <cstdint>

constexpr int TOKENS = 8192;
constexpr int INF    = 4096;
constexpr int RANK   = 1024;
constexpr int OUTF   = 4096;

// ---------------- static device scratch (no allocs allowed) ----------------
__device__ __nv_bfloat16 g_x1[(size_t)TOKENS * INF];
__device__ __nv_bfloat16 g_x2[(size_t)TOKENS * INF];
__device__ __nv_bfloat16 g_x3[(size_t)TOKENS * INF];
__device__ __nv_bfloat16 g_w1[(size_t)RANK * INF];
__device__ __nv_bfloat16 g_w2[(size_t)RANK * INF];
__device__ __nv_bfloat16 g_w3[(size_t)RANK * INF];
__device__ __nv_bfloat16 g_a1[(size_t)OUTF * RANK];
__device__ __nv_bfloat16 g_a2[(size_t)OUTF * RANK];
__device__ __nv_bfloat16 g_q [(size_t)TOKENS * RANK];
__device__ float         g_y [(size_t)TOKENS * RANK];
__device__ int           g_amax_bits;

// ---------------- low-level helpers (baseline PTX, sm_80+) ----------------
__device__ __forceinline__ uint32_t smem_u32(const void* p) {
    uint32_t a;
    asm("{ .reg .u64 t; cvta.to.shared.u64 t, %1; cvt.u32.u64 %0, t; }" : "=r"(a) : "l"(p));
    return a;
}
__device__ __forceinline__ void cpa16(uint32_t s, const void* g) {
    asm volatile("cp.async.cg.shared.global [%0], [%1], 16;" :: "r"(s), "l"(g));
}
__device__ __forceinline__ void cpa_commit() { asm volatile("cp.async.commit_group;" ::: "memory"); }
__device__ __forceinline__ void cpa_wait1()  { asm volatile("cp.async.wait_group 1;" ::: "memory"); }

__device__ __forceinline__ void ldsm4(uint32_t* r, uint32_t a) {
    asm volatile("ldmatrix.sync.aligned.m8n8.x4.shared.b16 {%0,%1,%2,%3}, [%4];"
                 : "=r"(r[0]), "=r"(r[1]), "=r"(r[2]), "=r"(r[3]) : "r"(a));
}
__device__ __forceinline__ void mma_bf16(float* d, const uint32_t* a, const uint32_t* b) {
    asm volatile(
        "mma.sync.aligned.m16n8k16.row.col.f32.bf16.bf16.f32 "
        "{%0,%1,%2,%3}, {%4,%5,%6,%7}, {%8,%9}, {%0,%1,%2,%3};"
        : "+f"(d[0]), "+f"(d[1]), "+f"(d[2]), "+f"(d[3])
        : "r"(a[0]), "r"(a[1]), "r"(a[2]), "r"(a[3]), "r"(b[0]), "r"(b[1]));
}
// 128B rows of 8 x 16B chunks; xor-swizzle -> conflict-free ldmatrix & stores
__device__ __forceinline__ uint32_t sw(uint32_t row, uint32_t ch) {
    return row * 128u + ((ch ^ (row & 7u)) * 16u);
}

// ---------------- prep kernels (float4-vectorized) ----------------
__global__ void k_split3(const float* __restrict__ s, __nv_bfloat16* __restrict__ d1,
                         __nv_bfloat16* __restrict__ d2, __nv_bfloat16* __restrict__ d3, int n4) {
    int i = blockIdx.x * blockDim.x + threadIdx.x;
    if (i >= n4) return;
    float4 v = reinterpret_cast<const float4*>(s)[i];
    float f[4] = {v.x, v.y, v.z, v.w};
    __nv_bfloat16 h1[4], h2[4], h3[4];
#pragma unroll
    for (int j = 0; j < 4; j++) {
        h1[j] = __float2bfloat16_rn(f[j]);
        float r  = __fsub_rn(f[j], __bfloat162float(h1[j]));   // exact
        h2[j] = __float2bfloat16_rn(r);
        float r2 = __fsub_rn(r, __bfloat162float(h2[j]));      // exact
        h3[j] = __float2bfloat16_rn(r2);                       // exact (27>=24 bits)
    }
    reinterpret_cast<__nv_bfloat162*>(d1)[i*2]   = __halves2bfloat162(h1[0], h1[1]);
    reinterpret_cast<__nv_bfloat162*>(d1)[i*2+1] = __halves2bfloat162(h1[2], h1[3]);
    reinterpret_cast<__nv_bfloat162*>(d2)[i*2]   = __halves2bfloat162(h2[0], h2[1]);
    reinterpret_cast<__nv_bfloat162*>(d2)[i*2+1] = __halves2bfloat162(h2[2], h2[3]);
    reinterpret_cast<__nv_bfloat162*>(d3)[i*2]   = __halves2bfloat162(h3[0], h3[1]);
    reinterpret_cast<__nv_bfloat162*>(d3)[i*2+1] = __halves2bfloat162(h3[2], h3[3]);
}

// 2-limb split; global thread 0 also resets the amax accumulator (runs before gemm1).
__global__ void k_split2(const float* __restrict__ s, __nv_bfloat16* __restrict__ d1,
                         __nv_bfloat16* __restrict__ d2, int n4) {
    int i = blockIdx.x * blockDim.x + threadIdx.x;
    if (i == 0) g_amax_bits = 0;
    if (i >= n4) return;
    float4 v = reinterpret_cast<const float4*>(s)[i];
    float f[4] = {v.x, v.y, v.z, v.w};
    __nv_bfloat16 h1[4], h2[4];
#pragma unroll
    for (int j = 0; j < 4; j++) {
        h1[j] = __float2bfloat16_rn(f[j]);
        float r = __fsub_rn(f[j], __bfloat162float(h1[j]));
        h2[j] = __float2bfloat16_rn(r);
    }
    reinterpret_cast<__nv_bfloat162*>(d1)[i*2]   = __halves2bfloat162(h1[0], h1[1]);
    reinterpret_cast<__nv_bfloat162*>(d1)[i*2+1] = __halves2bfloat162(h1[2], h1[3]);
    reinterpret_cast<__nv_bfloat162*>(d2)[i*2]   = __halves2bfloat162(h2[0], h2[1]);
    reinterpret_cast<__nv_bfloat162*>(d2)[i*2+1] = __halves2bfloat162(h2[2], h2[3]);
}

// q = clip(round(y/scale), -4, 3), exact small integers in bf16
__global__ void k_quant(const float* __restrict__ y, __nv_bfloat16* __restrict__ q, int n4) {
    const float amax  = __int_as_float(g_amax_bits);
    const float scale = __fdiv_rn(fmaxf(amax, 1e-8f), 3.0f);
    int i = blockIdx.x * blockDim.x + threadIdx.x;
    if (i >= n4) return;
    float4 v = reinterpret_cast<const float4*>(y)[i];
    float q0 = fminf(fmaxf(rintf(__fdiv_rn(v.x, scale)), -4.f), 3.f);
    float q1 = fminf(fmaxf(rintf(__fdiv_rn(v.y, scale)), -4.f), 3.f);
    float q2 = fminf(fmaxf(rintf(__fdiv_rn(v.z, scale)), -4.f), 3.f);
    float q3 = fminf(fmaxf(rintf(__fdiv_rn(v.w, scale)), -4.f), 3.f);
    reinterpret_cast<__nv_bfloat162*>(q)[i*2] =
        __halves2bfloat162(__float2bfloat16_rn(q0), __float2bfloat16_rn(q1));
    reinterpret_cast<__nv_bfloat162*>(q)[i*2+1] =
        __halves2bfloat162(__float2bfloat16_rn(q2), __float2bfloat16_rn(q3));
}

// ---------------------------------------------------------------------------
// GEMM1: y = x @ B_w^T via 6 limb products on mma.sync bf16 (identical to R9).
// Block 128x64, BK=64, 256 threads = 8 warps (4m x 2n), warp tile 32x32.
// ---------------------------------------------------------------------------
constexpr int G1_STAGE = 3 * 16384 + 3 * 8192;
constexpr int G1_SMEM  = 3 * G1_STAGE;           // 216 KB

__global__ __launch_bounds__(256, 1)
void gemm1_mma(const __nv_bfloat16* __restrict__ X1, const __nv_bfloat16* __restrict__ X2,
               const __nv_bfloat16* __restrict__ X3, const __nv_bfloat16* __restrict__ W1,
               const __nv_bfloat16* __restrict__ W2, const __nv_bfloat16* __restrict__ W3,
               float* __restrict__ Y)
{
    extern __shared__ char smem_raw[];
    const uint32_t sbu = smem_u32(smem_raw);
    const int tid = threadIdx.x, lane = tid & 31, wid = tid >> 5;
    const int wm = wid & 3, wn = wid >> 2;
    const int m0 = blockIdx.y * 128, n0 = blockIdx.x * 64;

    const __nv_bfloat16* AP[3] = {X1, X2, X3};
    const __nv_bfloat16* BP[3] = {W1, W2, W3};

    float acc[32], cmp[32];
#pragma unroll
    for (int c = 0; c < 32; c++) { acc[c] = 0.f; cmp[c] = 0.f; }

    auto load_stage = [&](int kt, int buf) {
        const uint32_t sb = sbu + buf * G1_STAGE;
        const int k0 = kt * 64;
#pragma unroll
        for (int l = 0; l < 3; l++) {
#pragma unroll
            for (int it = 0; it < 4; it++) {
                int i = tid + it * 256;
                int row = i >> 3, ch = i & 7;
                cpa16(sb + l * 16384 + sw(row, ch),
                      AP[l] + (size_t)(m0 + row) * INF + k0 + ch * 8);
            }
#pragma unroll
            for (int it = 0; it < 2; it++) {
                int i = tid + it * 256;
                int row = i >> 3, ch = i & 7;
                cpa16(sb + 49152 + l * 8192 + sw(row, ch),
                      BP[l] + (size_t)(n0 + row) * INF + k0 + ch * 8);
            }
        }
    };

    load_stage(0, 0); cpa_commit();
    load_stage(1, 1); cpa_commit();

    const int tA = lane >> 3, rA = lane & 7;
    const uint32_t arow  = wm * 32 + (tA & 1) * 8 + rA;
    const uint32_t brow0 = wn * 32 +      ((lane >> 4) & 1) * 8 + (lane & 7);
    const uint32_t brow1 = wn * 32 + 16 + ((lane >> 4) & 1) * 8 + (lane & 7);
    const uint32_t bch   = (lane >> 3) & 1;

    for (int kt = 0; kt < 64; kt++) {
        cpa_wait1();
        __syncthreads();

        const uint32_t sb = sbu + (kt % 3) * G1_STAGE;
        float chunk[32];
#pragma unroll
        for (int c = 0; c < 32; c++) chunk[c] = 0.f;

#pragma unroll
        for (int al = 2; al >= 0; al--) {
            uint32_t aF[2][4][4];
            const uint32_t ta = sb + al * 16384;
#pragma unroll
            for (int mi = 0; mi < 2; mi++)
#pragma unroll
                for (int ks = 0; ks < 4; ks++)
                    ldsm4(aF[mi][ks], ta + sw(arow + mi * 16, ks * 2 + (tA >> 1)));
            const int nb = (al == 0) ? 3 : (al == 1 ? 2 : 1);
#pragma unroll
            for (int bl = 2; bl >= 0; bl--) {
                if (bl >= nb) continue;
                const uint32_t tb = sb + 49152 + bl * 8192;
#pragma unroll
                for (int ks = 0; ks < 4; ks++) {
                    uint32_t bF[4], bG[4];
                    ldsm4(bF, tb + sw(brow0, ks * 2 + bch));
                    ldsm4(bG, tb + sw(brow1, ks * 2 + bch));
                    mma_bf16(&chunk[0],  aF[0][ks], bF + 0);
                    mma_bf16(&chunk[16], aF[1][ks], bF + 0);
                    mma_bf16(&chunk[4],  aF[0][ks], bF + 2);
                    mma_bf16(&chunk[20], aF[1][ks], bF + 2);
                    mma_bf16(&chunk[8],  aF[0][ks], bG + 0);
                    mma_bf16(&chunk[24], aF[1][ks], bG + 0);
                    mma_bf16(&chunk[12], aF[0][ks], bG + 2);
                    mma_bf16(&chunk[28], aF[1][ks], bG + 2);
                }
            }
        }

#pragma unroll
        for (int c = 0; c < 32; c++) {
            float yk = __fsub_rn(chunk[c], cmp[c]);
            float t  = __fadd_rn(acc[c], yk);
            cmp[c]   = __fsub_rn(__fsub_rn(t, acc[c]), yk);
            acc[c]   = t;
        }

        if (kt + 2 < 64) load_stage(kt + 2, (kt + 2) % 3);
        cpa_commit();
    }

    float v[32];
    float lmax = 0.f;
#pragma unroll
    for (int c = 0; c < 32; c++) {
        v[c] = __fsub_rn(acc[c], cmp[c]);
        lmax = fmaxf(lmax, fabsf(v[c]));
    }
#pragma unroll
    for (int o = 16; o > 0; o >>= 1)
        lmax = fmaxf(lmax, __shfl_xor_sync(0xffffffffu, lmax, o));
    if (lane == 0) atomicMax(&g_amax_bits, __float_as_int(lmax));

    const int rbase = m0 + wm * 32 + (lane >> 2);
    const int cbase = n0 + wn * 32 + (lane & 3) * 2;
#pragma unroll
    for (int mi = 0; mi < 2; mi++)
#pragma unroll
        for (int ni = 0; ni < 4; ni++) {
            const float* f = &v[mi * 16 + ni * 4];
            float* p0 = Y + (size_t)(rbase + mi * 16)     * RANK + cbase + ni * 8;
            float* p1 = Y + (size_t)(rbase + mi * 16 + 8) * RANK + cbase + ni * 8;
            *reinterpret_cast<float2*>(p0) = make_float2(f[0], f[1]);
            *reinterpret_cast<float2*>(p1) = make_float2(f[2], f[3]);
        }
}

// ---------------------------------------------------------------------------
// GEMM2: out = (q @ A^T) * scale + bias, 2 limb products, plain accumulation.
// Block 128x64, BK=64, 256 threads = 8 warps (4m x 2n), warp tile 32x32.
// (bf16 HMMA path -- IMMA measured ~5x slower per instruction on sm_103a.)
// ---------------------------------------------------------------------------
constexpr int G2_STAGE = 16384 + 2 * 8192;   // q (128x64) + a1,a2 (64x64)
constexpr int G2_SMEM  = 3 * G2_STAGE;       // 96 KB

__global__ __launch_bounds__(256, 1)
void gemm2_mma(const __nv_bfloat16* __restrict__ Q, const __nv_bfloat16* __restrict__ A1,
               const __nv_bfloat16* __restrict__ A2, const float* __restrict__ bias,
               float* __restrict__ Out)
{
    extern __shared__ char smem_raw[];
    const uint32_t sbu = smem_u32(smem_raw);
    const int tid = threadIdx.x, lane = tid & 31, wid = tid >> 5;
    const int wm = wid & 3, wn = wid >> 2;
    const int m0 = blockIdx.y * 128, n0 = blockIdx.x * 64;

    const __nv_bfloat16* BP[2] = {A1, A2};

    float acc[32];
#pragma unroll
    for (int c = 0; c < 32; c++) acc[c] = 0.f;

    auto load_stage = [&](int kt, int buf) {
        const uint32_t sb = sbu + buf * G2_STAGE;
        const int k0 = kt * 64;
#pragma unroll
        for (int it = 0; it < 4; it++) {
            int i = tid + it * 256;
            int row = i >> 3, ch = i & 7;
            cpa16(sb + sw(row, ch), Q + (size_t)(m0 + row) * RANK + k0 + ch * 8);
        }
#pragma unroll
        for (int l = 0; l < 2; l++)
#pragma unroll
            for (int it = 0; it < 2; it++) {
                int i = tid + it * 256;
                int row = i >> 3, ch = i & 7;
                cpa16(sb + 16384 + l * 8192 + sw(row, ch),
                      BP[l] + (size_t)(n0 + row) * RANK + k0 + ch * 8);
            }
    };

    load_stage(0, 0); cpa_commit();
    load_stage(1, 1); cpa_commit();

    const int tA = lane >> 3, rA = lane & 7;
    const uint32_t arow  = wm * 32 + (tA & 1) * 8 + rA;
    const uint32_t brow0 = wn * 32 +      ((lane >> 4) & 1) * 8 + (lane & 7);
    const uint32_t brow1 = wn * 32 + 16 + ((lane >> 4) & 1) * 8 + (lane & 7);
    const uint32_t bch   = (lane >> 3) & 1;

    for (int kt = 0; kt < 16; kt++) {
        cpa_wait1();
        __syncthreads();

        const uint32_t sb = sbu + (kt % 3) * G2_STAGE;
        uint32_t aF[2][4][4];
#pragma unroll
        for (int mi = 0; mi < 2; mi++)
#pragma unroll
            for (int ks = 0; ks < 4; ks++)
                ldsm4(aF[mi][ks], sb + sw(arow + mi * 16, ks * 2 + (tA >> 1)));
#pragma unroll
        for (int bl = 1; bl >= 0; bl--) {
            const uint32_t tb = sb + 16384 + bl * 8192;
#pragma unroll
            for (int ks = 0; ks < 4; ks++) {
                uint32_t bF[4], bG[4];
                ldsm4(bF, tb + sw(brow0, ks * 2 + bch));
                ldsm4(bG, tb + sw(brow1, ks * 2 + bch));
                mma_bf16(&acc[0],  aF[0][ks], bF + 0);
                mma_bf16(&acc[16], aF[1][ks], bF + 0);
                mma_bf16(&acc[4],  aF[0][ks], bF + 2);
                mma_bf16(&acc[20], aF[1][ks], bF + 2);
                mma_bf16(&acc[8],  aF[0][ks], bG + 0);
                mma_bf16(&acc[24], aF[1][ks], bG + 0);
                mma_bf16(&acc[12], aF[0][ks], bG + 2);
                mma_bf16(&acc[28], aF[1][ks], bG + 2);
            }
        }

        if (kt + 2 < 16) load_stage(kt + 2, (kt + 2) % 3);
        cpa_commit();
    }

    const float amax  = __int_as_float(g_amax_bits);
    const float scale = __fdiv_rn(fmaxf(amax, 1e-8f), 3.0f);
    const int rbase = m0 + wm * 32 + (lane >> 2);
    const int cbase = n0 + wn * 32 + (lane & 3) * 2;
#pragma unroll
    for (int mi = 0; mi < 2; mi++)
#pragma unroll
        for (int ni = 0; ni < 4; ni++) {
            const float* f = &acc[mi * 16 + ni * 4];
            const int col = cbase + ni * 8;
            const float b0 = __ldg(bias + col), b1 = __ldg(bias + col + 1);
            float* p0 = Out + (size_t)(rbase + mi * 16)     * OUTF + col;
            float* p1 = Out + (size_t)(rbase + mi * 16 + 8) * OUTF + col;
            *reinterpret_cast<float2*>(p0) =
                make_float2(__fadd_rn(__fmul_rn(f[0], scale), b0),
                            __fadd_rn(__fmul_rn(f[1], scale), b1));
            *reinterpret_cast<float2*>(p1) =
                make_float2(__fadd_rn(__fmul_rn(f[2], scale), b0),
                            __fadd_rn(__fmul_rn(f[3], scale), b1));
        }
}

// ---------------------------------------------------------------------------
extern "C" void kernel_launch(void* const* d_in, const int* in_sizes, int n_in,
                              void* d_out, int out_size)
{
    const float* input = (const float*)d_in[0];
    const float* B_w   = (const float*)d_in[1];
    const float* A_w   = (const float*)d_in[2];
    const float* A_b   = (const float*)d_in[3];
    float*       out   = (float*)d_out;

    __nv_bfloat16 *x1, *x2, *x3, *w1, *w2, *w3, *a1, *a2, *q;
    float* y;
    cudaGetSymbolAddress((void**)&x1, g_x1); cudaGetSymbolAddress((void**)&x2, g_x2);
    cudaGetSymbolAddress((void**)&x3, g_x3); cudaGetSymbolAddress((void**)&w1, g_w1);
    cudaGetSymbolAddress((void**)&w2, g_w2); cudaGetSymbolAddress((void**)&w3, g_w3);
    cudaGetSymbolAddress((void**)&a1, g_a1); cudaGetSymbolAddress((void**)&a2, g_a2);
    cudaGetSymbolAddress((void**)&q,  g_q);  cudaGetSymbolAddress((void**)&y,  g_y);

    cudaFuncSetAttribute(gemm1_mma, cudaFuncAttributeMaxDynamicSharedMemorySize, G1_SMEM);
    cudaFuncSetAttribute(gemm2_mma, cudaFuncAttributeMaxDynamicSharedMemorySize, G2_SMEM);

    {   // limb splits (k_split2 also resets g_amax_bits before gemm1)
        int n4 = TOKENS * INF / 4;
        k_split3<<<(n4 + 255) / 256, 256>>>(input, x1, x2, x3, n4);
        n4 = RANK * INF / 4;
        k_split3<<<(n4 + 255) / 256, 256>>>(B_w, w1, w2, w3, n4);
        n4 = OUTF * RANK / 4;
        k_split2<<<(n4 + 255) / 256, 256>>>(A_w, a1, a2, n4);
    }

    {   // y = x @ B_w^T  (tensor cores, fused amax)
        dim3 grid(RANK / 64, TOKENS / 128);
        gemm1_mma<<<grid, 256, G1_SMEM>>>(x1, x2, x3, w1, w2, w3, y);
    }

    {   // q = clip(round(y/scale))
        const int n4 = TOKENS * RANK / 4;
        k_quant<<<(n4 + 255) / 256, 256>>>(y, q, n4);
    }

    {   // out = q @ A^T * scale + bias
        dim3 grid(OUTF / 64, TOKENS / 128);
        gemm2_mma<<<grid, 256, G2_SMEM>>>(q, a1, a2, A_b, out);
    }
}